// round 2
// baseline (speedup 1.0000x reference)
#include <cuda_runtime.h>
#include <cuda_fp16.h>
#include <cstdint>

static constexpr int KDIM = 4096;
static constexpr int NDIM = 4096;
static constexpr int BK   = 32;
static constexpr int NCH  = KDIM / BK;   // 128 k-chunks
static constexpr int ROWB = 80;          // smem row stride bytes (32 halves + 16B pad)

// smem offsets (bytes)
static constexpr int OFF_A0  = 0;
static constexpr int OFF_A1  = 10240;
static constexpr int OFF_W0  = 20480;
static constexpr int OFF_W1  = 30720;
static constexpr int OFF_BS  = 40960;    // bias_linear+bias_extra [128] f32
static constexpr int OFF_GW  = 41472;
static constexpr int OFF_GB  = 41984;
static constexpr int OFF_RED = 42496;    // float2[128][4]
static constexpr int SMEM_BYTES = OFF_RED + 4096;  // 46592 < 48KB static

#define DINL __device__ __forceinline__

DINL uint32_t smem_u32(const void* p) {
    uint32_t a;
    asm("{ .reg .u64 t; cvta.to.shared.u64 t, %1; cvt.u32.u64 %0, t; }" : "=r"(a) : "l"(p));
    return a;
}

#define LDMX4(d, addr)                                                              \
    asm volatile("ldmatrix.sync.aligned.m8n8.x4.shared.b16 {%0,%1,%2,%3}, [%4];"    \
        : "=r"((d)[0]), "=r"((d)[1]), "=r"((d)[2]), "=r"((d)[3]) : "r"(addr))

#define MMA16816(c, a, b0, b1)                                                      \
    asm volatile("mma.sync.aligned.m16n8k16.row.col.f32.f16.f16.f32 "               \
        "{%0,%1,%2,%3}, {%4,%5,%6,%7}, {%8,%9}, {%0,%1,%2,%3};"                     \
        : "+f"((c)[0]), "+f"((c)[1]), "+f"((c)[2]), "+f"((c)[3])                    \
        : "r"((a)[0]), "r"((a)[1]), "r"((a)[2]), "r"((a)[3]), "r"(b0), "r"(b1))

__global__ void __launch_bounds__(256, 1)
fused_gemm_mish_gn(const float* __restrict__ x, const float* __restrict__ w,
                   const float* __restrict__ bl, const float* __restrict__ be,
                   const float* __restrict__ gwp, const float* __restrict__ gbp,
                   float* __restrict__ out) {
    __shared__ __align__(16) unsigned char sm[SMEM_BYTES];
    const uint32_t sb = smem_u32(sm);

    const int tid  = threadIdx.x;
    const int lane = tid & 31;
    const int wid  = tid >> 5;
    const int wm   = wid & 1;    // 2 row-blocks of 64
    const int wn   = wid >> 1;   // 4 col-blocks of 32
    const int m0   = blockIdx.y << 7;
    const int n0   = blockIdx.x << 7;

    float* bs  = (float*)(sm + OFF_BS);
    float* gws = (float*)(sm + OFF_GW);
    float* gbs = (float*)(sm + OFF_GB);
    float2* red = (float2*)(sm + OFF_RED);

    if (tid < 128) {
        bs[tid]  = bl[n0 + tid] + be[n0 + tid];
        gws[tid] = gwp[n0 + tid];
        gbs[tid] = gbp[n0 + tid];
    }

    // ---- global load pointers: 4 float4 per thread per matrix per chunk ----
    const float* ap = x + (size_t)(m0 + (tid >> 3)) * KDIM + (tid & 7) * 4;
    const float* wp = w + (size_t)(n0 + (tid >> 3)) * KDIM + (tid & 7) * 4;
    const uint32_t sts_off = (uint32_t)(tid >> 3) * ROWB + (tid & 7) * 8;

    float4 fa[4], fw[4];
    auto ldg_chunk = [&](int kc) {
#pragma unroll
        for (int i = 0; i < 4; ++i) {
            fa[i] = *(const float4*)(ap + (size_t)(32 * i) * KDIM + kc * BK);
            fw[i] = *(const float4*)(wp + (size_t)(32 * i) * KDIM + kc * BK);
        }
    };
    auto sts_chunk = [&](int buf) {
        unsigned char* a_s = sm + (buf ? OFF_A1 : OFF_A0) + sts_off;
        unsigned char* w_s = sm + (buf ? OFF_W1 : OFF_W0) + sts_off;
#pragma unroll
        for (int i = 0; i < 4; ++i) {
            __half2 h0 = __floats2half2_rn(fa[i].x, fa[i].y);
            __half2 h1 = __floats2half2_rn(fa[i].z, fa[i].w);
            uint2 va = {*(uint32_t*)&h0, *(uint32_t*)&h1};
            h0 = __floats2half2_rn(fw[i].x, fw[i].y);
            h1 = __floats2half2_rn(fw[i].z, fw[i].w);
            uint2 vw = {*(uint32_t*)&h0, *(uint32_t*)&h1};
            *(uint2*)(a_s + i * 32 * ROWB) = va;
            *(uint2*)(w_s + i * 32 * ROWB) = vw;
        }
    };

    float acc[4][4][4];
#pragma unroll
    for (int i = 0; i < 4; ++i)
#pragma unroll
        for (int j = 0; j < 4; ++j)
#pragma unroll
            for (int k = 0; k < 4; ++k) acc[i][j][k] = 0.f;

    const uint32_t a_lm = sb + (uint32_t)((wm * 64 + (lane & 15)) * ROWB + (lane >> 4) * 16);
    const uint32_t w_lm = sb + (uint32_t)((wn * 32 + (lane & 15)) * ROWB + (lane >> 4) * 16);

    auto do_mma = [&](int buf) {
        const uint32_t abase = a_lm + (buf ? OFF_A1 : OFF_A0);
        const uint32_t bbase = w_lm + (buf ? OFF_W1 : OFF_W0);
#pragma unroll
        for (int kt = 0; kt < 2; ++kt) {
            uint32_t af[4][4], bf[2][4];
#pragma unroll
            for (int mt = 0; mt < 4; ++mt) LDMX4(af[mt], abase + mt * 16 * ROWB + kt * 32);
#pragma unroll
            for (int nb = 0; nb < 2; ++nb) LDMX4(bf[nb], bbase + nb * 16 * ROWB + kt * 32);
#pragma unroll
            for (int mt = 0; mt < 4; ++mt)
#pragma unroll
                for (int nt = 0; nt < 4; ++nt)
                    MMA16816(acc[mt][nt], af[mt], bf[nt >> 1][nt & 1], bf[nt >> 1][(nt & 1) + 2]);
        }
    };

    // ---- pipelined mainloop ----
    ldg_chunk(0);
    sts_chunk(0);
    __syncthreads();
#pragma unroll 1
    for (int kc = 0; kc < NCH; ++kc) {
        if (kc + 1 < NCH) ldg_chunk(kc + 1);
        do_mma(kc & 1);
        if (kc + 1 < NCH) sts_chunk((kc + 1) & 1);
        __syncthreads();
    }

    // ---- fused epilogue: bias -> hardtanh -> mish -> GroupNorm (group == 128 ch) ----
    float ps[4][2], pq[4][2];
#pragma unroll
    for (int mt = 0; mt < 4; ++mt)
#pragma unroll
        for (int rr = 0; rr < 2; ++rr) { ps[mt][rr] = 0.f; pq[mt][rr] = 0.f; }

#pragma unroll
    for (int mt = 0; mt < 4; ++mt)
#pragma unroll
        for (int nt = 0; nt < 4; ++nt)
#pragma unroll
            for (int rr = 0; rr < 2; ++rr)
#pragma unroll
                for (int j = 0; j < 2; ++j) {
                    int n = wn * 32 + nt * 8 + (lane & 3) * 2 + j;
                    float y = acc[mt][nt][rr * 2 + j] + bs[n];
                    y = fminf(1.0f, fmaxf(-1.0f, y));        // hardtanh
                    float z = 1.0f + __expf(y);              // mish: y*(z^2-1)/(z^2+1)
                    float z2 = z * z;
                    float m = y * __fdividef(z2 - 1.0f, z2 + 1.0f);
                    acc[mt][nt][rr * 2 + j] = m;
                    ps[mt][rr] += m;
                    pq[mt][rr] = fmaf(m, m, pq[mt][rr]);
                }

    // reduce across the 4 lanes sharing each row, then across the 4 n-warps via smem
#pragma unroll
    for (int mt = 0; mt < 4; ++mt)
#pragma unroll
        for (int rr = 0; rr < 2; ++rr) {
            float s = ps[mt][rr], q = pq[mt][rr];
            s += __shfl_xor_sync(0xFFFFFFFFu, s, 1);
            q += __shfl_xor_sync(0xFFFFFFFFu, q, 1);
            s += __shfl_xor_sync(0xFFFFFFFFu, s, 2);
            q += __shfl_xor_sync(0xFFFFFFFFu, q, 2);
            if ((lane & 3) == 0) {
                int row = wm * 64 + mt * 16 + (lane >> 2) + rr * 8;
                red[row * 4 + wn] = make_float2(s, q);
            }
        }
    __syncthreads();

#pragma unroll
    for (int mt = 0; mt < 4; ++mt)
#pragma unroll
        for (int rr = 0; rr < 2; ++rr) {
            int row = wm * 64 + mt * 16 + (lane >> 2) + rr * 8;
            float2 r0 = red[row * 4 + 0], r1 = red[row * 4 + 1];
            float2 r2 = red[row * 4 + 2], r3 = red[row * 4 + 3];
            float s = r0.x + r1.x + r2.x + r3.x;
            float q = r0.y + r1.y + r2.y + r3.y;
            float mean = s * 0.0078125f;
            float var  = fmaf(-mean, mean, q * 0.0078125f);
            float rs   = rsqrtf(var + 1e-5f);
            float* orow = out + (size_t)(m0 + row) * NDIM + n0;
#pragma unroll
            for (int nt = 0; nt < 4; ++nt) {
                int n = wn * 32 + nt * 8 + (lane & 3) * 2;
                float2 o;
                o.x = fmaf((acc[mt][nt][rr * 2 + 0] - mean) * rs, gws[n + 0], gbs[n + 0]);
                o.y = fmaf((acc[mt][nt][rr * 2 + 1] - mean) * rs, gws[n + 1], gbs[n + 1]);
                *(float2*)(orow + n) = o;
            }
        }
}

extern "C" void kernel_launch(void* const* d_in, const int* in_sizes, int n_in,
                              void* d_out, int out_size) {
    const float* x  = (const float*)d_in[0];
    const float* w  = (const float*)d_in[1];
    const float* bl = (const float*)d_in[2];
    const float* be = (const float*)d_in[3];
    const float* gw = (const float*)d_in[4];
    const float* gb = (const float*)d_in[5];
    float* out = (float*)d_out;

    int B = in_sizes[0] / KDIM;          // 8192
    dim3 grid(NDIM / 128, B / 128);      // (32, 64)
    fused_gemm_mish_gn<<<grid, 256>>>(x, w, bl, be, gw, gb, out);
}

// round 3
// speedup vs baseline: 1.1027x; 1.1027x over previous
#include <cuda_runtime.h>
#include <cuda_fp16.h>
#include <cstdint>

static constexpr int KDIM = 4096;
static constexpr int NDIM = 4096;
static constexpr int BDIM = 8192;
static constexpr int BK   = 64;
static constexpr int NCH  = KDIM / BK;     // 64 chunks
static constexpr int ROWB = 144;           // 128B data + 16B pad per smem row
static constexpr int STAGE_A = 0;
static constexpr int STAGE_W = 128 * ROWB;             // 18432
static constexpr int STAGE_BYTES = 2 * 128 * ROWB;     // 36864
static constexpr int NSTAGE = 4;
static constexpr int OFF_BS  = NSTAGE * STAGE_BYTES;   // 147456
static constexpr int OFF_GW  = OFF_BS + 512;
static constexpr int OFF_GB  = OFF_GW + 512;
static constexpr int OFF_RED = OFF_GB + 512;
static constexpr int SMEM_BYTES = OFF_RED + 4096;      // 153088

__device__ __align__(16) __half g_xh[(size_t)BDIM * KDIM];   // 64 MB
__device__ __align__(16) __half g_wh[(size_t)NDIM * KDIM];   // 32 MB

#define DINL __device__ __forceinline__

DINL uint32_t smem_u32(const void* p) {
    uint32_t a;
    asm("{ .reg .u64 t; cvta.to.shared.u64 t, %1; cvt.u32.u64 %0, t; }" : "=r"(a) : "l"(p));
    return a;
}
DINL void cp_async16(uint32_t s, const void* g) {
    asm volatile("cp.async.cg.shared.global [%0], [%1], 16;" :: "r"(s), "l"(g) : "memory");
}
DINL void cp_commit() { asm volatile("cp.async.commit_group;" ::: "memory"); }
template <int N> DINL void cp_wait() { asm volatile("cp.async.wait_group %0;" :: "n"(N) : "memory"); }

#define LDMX4(d, addr)                                                              \
    asm volatile("ldmatrix.sync.aligned.m8n8.x4.shared.b16 {%0,%1,%2,%3}, [%4];"    \
        : "=r"((d)[0]), "=r"((d)[1]), "=r"((d)[2]), "=r"((d)[3]) : "r"(addr))

#define MMA16816(c, a, b0, b1)                                                      \
    asm volatile("mma.sync.aligned.m16n8k16.row.col.f32.f16.f16.f32 "               \
        "{%0,%1,%2,%3}, {%4,%5,%6,%7}, {%8,%9}, {%0,%1,%2,%3};"                     \
        : "+f"((c)[0]), "+f"((c)[1]), "+f"((c)[2]), "+f"((c)[3])                    \
        : "r"((a)[0]), "r"((a)[1]), "r"((a)[2]), "r"((a)[3]), "r"(b0), "r"(b1))

// ---------------- fp32 -> fp16 pre-convert ----------------
__global__ void __launch_bounds__(256) cvt_kernel(const float* __restrict__ src,
                                                  __half* __restrict__ dst) {
    size_t i = ((size_t)blockIdx.x * 256 + threadIdx.x) * 8;
    float4 f0 = *(const float4*)(src + i);
    float4 f1 = *(const float4*)(src + i + 4);
    __half2 h0 = __floats2half2_rn(f0.x, f0.y);
    __half2 h1 = __floats2half2_rn(f0.z, f0.w);
    __half2 h2 = __floats2half2_rn(f1.x, f1.y);
    __half2 h3 = __floats2half2_rn(f1.z, f1.w);
    uint4 v = {*(uint32_t*)&h0, *(uint32_t*)&h1, *(uint32_t*)&h2, *(uint32_t*)&h3};
    *(uint4*)(dst + i) = v;
}

// ---------------- fused GEMM + bias + hardtanh + mish + GroupNorm ----------------
__global__ void __launch_bounds__(256, 1)
fused_gemm_mish_gn(const float* __restrict__ bl, const float* __restrict__ be,
                   const float* __restrict__ gwp, const float* __restrict__ gbp,
                   float* __restrict__ out) {
    extern __shared__ __align__(16) unsigned char sm[];
    const uint32_t sb = smem_u32(sm);

    const int tid  = threadIdx.x;
    const int lane = tid & 31;
    const int wid  = tid >> 5;
    const int wm   = wid & 1;     // 2 row-blocks of 64
    const int wn   = wid >> 1;    // 4 col-blocks of 32
    const int m0   = blockIdx.y << 7;
    const int n0   = blockIdx.x << 7;

    float* bs  = (float*)(sm + OFF_BS);
    float* gws = (float*)(sm + OFF_GW);
    float* gbs = (float*)(sm + OFF_GB);
    float2* red = (float2*)(sm + OFF_RED);

    if (tid < 128) {
        bs[tid]  = bl[n0 + tid] + be[n0 + tid];
        gws[tid] = gwp[n0 + tid];
        gbs[tid] = gbp[n0 + tid];
    }

    // ---- cp.async mapping: thread t loads 4x16B of row (t>>1), half (t&1) ----
    const int ld_row = tid >> 1;
    const int ld_cb  = (tid & 1) * 4;                  // 16B-block index base (0 or 4)
    const __half* a_g = g_xh + (size_t)(m0 + ld_row) * KDIM + ld_cb * 8;
    const __half* w_g = g_wh + (size_t)(n0 + ld_row) * KDIM + ld_cb * 8;
    const uint32_t sts_a = sb + STAGE_A + (uint32_t)ld_row * ROWB + ld_cb * 16;
    const uint32_t sts_w = sb + STAGE_W + (uint32_t)ld_row * ROWB + ld_cb * 16;

    auto issue_chunk = [&](int kc) {
        uint32_t so = (uint32_t)(kc & (NSTAGE - 1)) * STAGE_BYTES;
        const __half* ga = a_g + kc * BK;
        const __half* gw = w_g + kc * BK;
#pragma unroll
        for (int i = 0; i < 4; ++i) {
            cp_async16(sts_a + so + i * 16, ga + i * 8);
            cp_async16(sts_w + so + i * 16, gw + i * 8);
        }
    };

    float acc[4][4][4];
#pragma unroll
    for (int i = 0; i < 4; ++i)
#pragma unroll
        for (int j = 0; j < 4; ++j)
#pragma unroll
            for (int k = 0; k < 4; ++k) acc[i][j][k] = 0.f;

    const uint32_t a_lm = sb + STAGE_A + (uint32_t)((wm * 64 + (lane & 15)) * ROWB + (lane >> 4) * 16);
    const uint32_t w_lm = sb + STAGE_W + (uint32_t)((wn * 32 + (lane & 15)) * ROWB + (lane >> 4) * 16);

    auto do_mma = [&](int kc) {
        uint32_t so = (uint32_t)(kc & (NSTAGE - 1)) * STAGE_BYTES;
#pragma unroll
        for (int kt = 0; kt < 4; ++kt) {
            uint32_t af[4][4], bf[2][4];
#pragma unroll
            for (int mt = 0; mt < 4; ++mt) LDMX4(af[mt], a_lm + so + mt * 16 * ROWB + kt * 32);
#pragma unroll
            for (int nb = 0; nb < 2; ++nb) LDMX4(bf[nb], w_lm + so + nb * 16 * ROWB + kt * 32);
#pragma unroll
            for (int mt = 0; mt < 4; ++mt)
#pragma unroll
                for (int nt = 0; nt < 4; ++nt)
                    MMA16816(acc[mt][nt], af[mt], bf[nt >> 1][nt & 1], bf[nt >> 1][(nt & 1) + 2]);
        }
    };

    // ---- multistage pipeline ----
#pragma unroll
    for (int s = 0; s < NSTAGE - 1; ++s) { issue_chunk(s); cp_commit(); }
    cp_wait<NSTAGE - 2>();
    __syncthreads();

#pragma unroll 1
    for (int kc = 0; kc < NCH; ++kc) {
        if (kc + NSTAGE - 1 < NCH) { issue_chunk(kc + NSTAGE - 1); cp_commit(); }
        do_mma(kc);
        cp_wait<NSTAGE - 2>();
        __syncthreads();
    }

    // ---- fused epilogue: bias -> hardtanh -> mish -> GroupNorm (group == 128 ch) ----
    float ps[4][2], pq[4][2];
#pragma unroll
    for (int mt = 0; mt < 4; ++mt)
#pragma unroll
        for (int rr = 0; rr < 2; ++rr) { ps[mt][rr] = 0.f; pq[mt][rr] = 0.f; }

#pragma unroll
    for (int mt = 0; mt < 4; ++mt)
#pragma unroll
        for (int nt = 0; nt < 4; ++nt)
#pragma unroll
            for (int rr = 0; rr < 2; ++rr)
#pragma unroll
                for (int j = 0; j < 2; ++j) {
                    int n = wn * 32 + nt * 8 + (lane & 3) * 2 + j;
                    float y = acc[mt][nt][rr * 2 + j] + bs[n];
                    y = fminf(1.0f, fmaxf(-1.0f, y));        // hardtanh
                    float z = 1.0f + __expf(y);              // mish: y*(z^2-1)/(z^2+1)
                    float z2 = z * z;
                    float m = y * __fdividef(z2 - 1.0f, z2 + 1.0f);
                    acc[mt][nt][rr * 2 + j] = m;
                    ps[mt][rr] += m;
                    pq[mt][rr] = fmaf(m, m, pq[mt][rr]);
                }

#pragma unroll
    for (int mt = 0; mt < 4; ++mt)
#pragma unroll
        for (int rr = 0; rr < 2; ++rr) {
            float s = ps[mt][rr], q = pq[mt][rr];
            s += __shfl_xor_sync(0xFFFFFFFFu, s, 1);
            q += __shfl_xor_sync(0xFFFFFFFFu, q, 1);
            s += __shfl_xor_sync(0xFFFFFFFFu, s, 2);
            q += __shfl_xor_sync(0xFFFFFFFFu, q, 2);
            if ((lane & 3) == 0) {
                int row = wm * 64 + mt * 16 + (lane >> 2) + rr * 8;
                red[row * 4 + wn] = make_float2(s, q);
            }
        }
    __syncthreads();

#pragma unroll
    for (int mt = 0; mt < 4; ++mt)
#pragma unroll
        for (int rr = 0; rr < 2; ++rr) {
            int row = wm * 64 + mt * 16 + (lane >> 2) + rr * 8;
            float2 r0 = red[row * 4 + 0], r1 = red[row * 4 + 1];
            float2 r2 = red[row * 4 + 2], r3 = red[row * 4 + 3];
            float s = r0.x + r1.x + r2.x + r3.x;
            float q = r0.y + r1.y + r2.y + r3.y;
            float mean = s * 0.0078125f;
            float var  = fmaf(-mean, mean, q * 0.0078125f);
            float rs   = rsqrtf(var + 1e-5f);
            float* orow = out + (size_t)(m0 + row) * NDIM + n0;
#pragma unroll
            for (int nt = 0; nt < 4; ++nt) {
                int n = wn * 32 + nt * 8 + (lane & 3) * 2;
                float2 o;
                o.x = fmaf((acc[mt][nt][rr * 2 + 0] - mean) * rs, gws[n + 0], gbs[n + 0]);
                o.y = fmaf((acc[mt][nt][rr * 2 + 1] - mean) * rs, gws[n + 1], gbs[n + 1]);
                *(float2*)(orow + n) = o;
            }
        }
}

// ---------------- launch ----------------
extern "C" void kernel_launch(void* const* d_in, const int* in_sizes, int n_in,
                              void* d_out, int out_size) {
    const float* x  = (const float*)d_in[0];
    const float* w  = (const float*)d_in[1];
    const float* bl = (const float*)d_in[2];
    const float* be = (const float*)d_in[3];
    const float* gw = (const float*)d_in[4];
    const float* gb = (const float*)d_in[5];
    float* out = (float*)d_out;

    static __half* xh_p = nullptr;
    static __half* wh_p = nullptr;
    if (!xh_p) {
        cudaGetSymbolAddress((void**)&xh_p, g_xh);
        cudaGetSymbolAddress((void**)&wh_p, g_wh);
        cudaFuncSetAttribute(fused_gemm_mish_gn,
                             cudaFuncAttributeMaxDynamicSharedMemorySize, SMEM_BYTES);
    }

    cvt_kernel<<<(int)((size_t)BDIM * KDIM / 8 / 256), 256>>>(x, xh_p);
    cvt_kernel<<<(int)((size_t)NDIM * KDIM / 8 / 256), 256>>>(w, wh_p);

    dim3 grid(NDIM / 128, BDIM / 128);   // (32, 64)
    fused_gemm_mish_gn<<<grid, 256, SMEM_BYTES>>>(bl, be, gw, gb, out);
}

// round 4
// speedup vs baseline: 1.7240x; 1.5635x over previous
#include <cuda_runtime.h>
#include <cuda_fp16.h>
#include <cstdint>

static constexpr int KDIM = 4096;
static constexpr int NDIM = 4096;
static constexpr int BDIM = 8192;
static constexpr int BK   = 64;
static constexpr int NCH  = KDIM / BK;                 // 64 chunks
static constexpr int STAGE_A = 0;
static constexpr int STAGE_W = 128 * 128;              // 16384
static constexpr int STAGE_BYTES = 2 * 128 * 128;      // 32768
static constexpr int NSTAGE = 4;
static constexpr int OFF_BS  = NSTAGE * STAGE_BYTES;   // 131072
static constexpr int OFF_GW  = OFF_BS + 512;
static constexpr int OFF_GB  = OFF_GW + 512;
static constexpr int OFF_RED = OFF_GB + 512;
static constexpr int SMEM_BYTES = OFF_RED + 4096;      // 136704

__device__ __align__(16) __half g_xh[(size_t)BDIM * KDIM];   // 64 MB
__device__ __align__(16) __half g_wh[(size_t)NDIM * KDIM];   // 32 MB

#define DINL __device__ __forceinline__

DINL uint32_t smem_u32(const void* p) {
    uint32_t a;
    asm("{ .reg .u64 t; cvta.to.shared.u64 t, %1; cvt.u32.u64 %0, t; }" : "=r"(a) : "l"(p));
    return a;
}
DINL void cp_async16(uint32_t s, const void* g) {
    asm volatile("cp.async.cg.shared.global [%0], [%1], 16;" :: "r"(s), "l"(g) : "memory");
}
DINL void cp_commit() { asm volatile("cp.async.commit_group;" ::: "memory"); }
template <int N> DINL void cp_wait() { asm volatile("cp.async.wait_group %0;" :: "n"(N) : "memory"); }

#define LDMX4(d, addr)                                                              \
    asm volatile("ldmatrix.sync.aligned.m8n8.x4.shared.b16 {%0,%1,%2,%3}, [%4];"    \
        : "=r"((d)[0]), "=r"((d)[1]), "=r"((d)[2]), "=r"((d)[3]) : "r"(addr))

#define MMA16816(c, a, b0, b1)                                                      \
    asm volatile("mma.sync.aligned.m16n8k16.row.col.f32.f16.f16.f32 "               \
        "{%0,%1,%2,%3}, {%4,%5,%6,%7}, {%8,%9}, {%0,%1,%2,%3};"                     \
        : "+f"((c)[0]), "+f"((c)[1]), "+f"((c)[2]), "+f"((c)[3])                    \
        : "r"((a)[0]), "r"((a)[1]), "r"((a)[2]), "r"((a)[3]), "r"(b0), "r"(b1))

// ---------------- fp32 -> fp16 pre-convert ----------------
__global__ void __launch_bounds__(256) cvt_kernel(const float* __restrict__ src,
                                                  __half* __restrict__ dst) {
    size_t i = ((size_t)blockIdx.x * 256 + threadIdx.x) * 8;
    float4 f0 = *(const float4*)(src + i);
    float4 f1 = *(const float4*)(src + i + 4);
    __half2 h0 = __floats2half2_rn(f0.x, f0.y);
    __half2 h1 = __floats2half2_rn(f0.z, f0.w);
    __half2 h2 = __floats2half2_rn(f1.x, f1.y);
    __half2 h3 = __floats2half2_rn(f1.z, f1.w);
    uint4 v = {*(uint32_t*)&h0, *(uint32_t*)&h1, *(uint32_t*)&h2, *(uint32_t*)&h3};
    *(uint4*)(dst + i) = v;
}

// ---------------- fused GEMM + bias + hardtanh + mish + GroupNorm ----------------
__global__ void __launch_bounds__(512, 1)
fused_gemm_mish_gn(const float* __restrict__ bl, const float* __restrict__ be,
                   const float* __restrict__ gwp, const float* __restrict__ gbp,
                   float* __restrict__ out) {
    extern __shared__ __align__(16) unsigned char sm[];
    const uint32_t sb = smem_u32(sm);

    const int tid  = threadIdx.x;
    const int lane = tid & 31;
    const int wid  = tid >> 5;         // 16 warps
    const int wn   = wid & 3;          // 4 col-blocks of 32
    const int wm   = wid >> 2;         // 4 row-blocks of 32
    const int m0   = blockIdx.y << 7;
    const int n0   = blockIdx.x << 7;

    float* bs  = (float*)(sm + OFF_BS);
    float* gws = (float*)(sm + OFF_GW);
    float* gbs = (float*)(sm + OFF_GB);
    float2* red = (float2*)(sm + OFF_RED);

    if (tid < 128) {
        bs[tid]  = bl[n0 + tid] + be[n0 + tid];
        gws[tid] = gwp[n0 + tid];
        gbs[tid] = gbp[n0 + tid];
    }

    // ---- cp.async mapping: thread t -> row (t>>2), two 16B chunks (t&3)*2+{0,1} ----
    const int ld_row = tid >> 2;
    const int ld_cb  = (tid & 3) * 2;
    const uint32_t swz0 = (uint32_t)(ld_cb ^ (ld_row & 7));
    const uint32_t swz1 = (uint32_t)((ld_cb + 1) ^ (ld_row & 7));
    const __half* a_g = g_xh + (size_t)(m0 + ld_row) * KDIM + ld_cb * 8;
    const __half* w_g = g_wh + (size_t)(n0 + ld_row) * KDIM + ld_cb * 8;
    const uint32_t sts_a = sb + STAGE_A + (uint32_t)ld_row * 128;
    const uint32_t sts_w = sb + STAGE_W + (uint32_t)ld_row * 128;

    auto issue_chunk = [&](int kc) {
        uint32_t so = (uint32_t)(kc & (NSTAGE - 1)) * STAGE_BYTES;
        const __half* ga = a_g + kc * BK;
        const __half* gw = w_g + kc * BK;
        cp_async16(sts_a + so + swz0 * 16, ga);
        cp_async16(sts_a + so + swz1 * 16, ga + 8);
        cp_async16(sts_w + so + swz0 * 16, gw);
        cp_async16(sts_w + so + swz1 * 16, gw + 8);
    };

    float acc[2][4][4];
#pragma unroll
    for (int i = 0; i < 2; ++i)
#pragma unroll
        for (int j = 0; j < 4; ++j)
#pragma unroll
            for (int k = 0; k < 4; ++k) acc[i][j][k] = 0.f;

    // ldmatrix lane bases (row part); column chunk is kt-dependent, swizzled per lane
    const uint32_t a_row = sb + STAGE_A + (uint32_t)(wm * 32 + (lane & 15)) * 128;
    const uint32_t w_row = sb + STAGE_W + (uint32_t)(wn * 32 + (lane & 15)) * 128;
    const int lhalf = lane >> 4;        // 0/1: which 16B column-half the lane supplies
    const int lxor  = lane & 7;

    auto do_mma = [&](int kc) {
        uint32_t so = (uint32_t)(kc & (NSTAGE - 1)) * STAGE_BYTES;
#pragma unroll
        for (int kt = 0; kt < 4; ++kt) {
            uint32_t csw = (uint32_t)((kt * 2 + lhalf) ^ lxor) * 16;
            uint32_t af[2][4], bf[2][4];
            LDMX4(af[0], a_row + so + csw);
            LDMX4(af[1], a_row + so + 16 * 128 + csw);
            LDMX4(bf[0], w_row + so + csw);
            LDMX4(bf[1], w_row + so + 16 * 128 + csw);
#pragma unroll
            for (int mt = 0; mt < 2; ++mt)
#pragma unroll
                for (int nt = 0; nt < 4; ++nt)
                    MMA16816(acc[mt][nt], af[mt], bf[nt >> 1][nt & 1], bf[nt >> 1][(nt & 1) + 2]);
        }
    };

    // ---- multistage pipeline ----
#pragma unroll
    for (int s = 0; s < NSTAGE - 1; ++s) { issue_chunk(s); cp_commit(); }
    cp_wait<NSTAGE - 2>();
    __syncthreads();

#pragma unroll 1
    for (int kc = 0; kc < NCH; ++kc) {
        if (kc + NSTAGE - 1 < NCH) { issue_chunk(kc + NSTAGE - 1); cp_commit(); }
        do_mma(kc);
        cp_wait<NSTAGE - 2>();
        __syncthreads();
    }

    // ---- fused epilogue: bias -> hardtanh -> mish -> GroupNorm (group == 128 ch) ----
    float ps[2][2], pq[2][2];
#pragma unroll
    for (int mt = 0; mt < 2; ++mt)
#pragma unroll
        for (int rr = 0; rr < 2; ++rr) { ps[mt][rr] = 0.f; pq[mt][rr] = 0.f; }

#pragma unroll
    for (int mt = 0; mt < 2; ++mt)
#pragma unroll
        for (int nt = 0; nt < 4; ++nt)
#pragma unroll
            for (int rr = 0; rr < 2; ++rr)
#pragma unroll
                for (int j = 0; j < 2; ++j) {
                    int n = wn * 32 + nt * 8 + (lane & 3) * 2 + j;
                    float y = acc[mt][nt][rr * 2 + j] + bs[n];
                    y = fminf(1.0f, fmaxf(-1.0f, y));        // hardtanh
                    float z = 1.0f + __expf(y);              // mish: y*(z^2-1)/(z^2+1)
                    float z2 = z * z;
                    float m = y * __fdividef(z2 - 1.0f, z2 + 1.0f);
                    acc[mt][nt][rr * 2 + j] = m;
                    ps[mt][rr] += m;
                    pq[mt][rr] = fmaf(m, m, pq[mt][rr]);
                }

#pragma unroll
    for (int mt = 0; mt < 2; ++mt)
#pragma unroll
        for (int rr = 0; rr < 2; ++rr) {
            float s = ps[mt][rr], q = pq[mt][rr];
            s += __shfl_xor_sync(0xFFFFFFFFu, s, 1);
            q += __shfl_xor_sync(0xFFFFFFFFu, q, 1);
            s += __shfl_xor_sync(0xFFFFFFFFu, s, 2);
            q += __shfl_xor_sync(0xFFFFFFFFu, q, 2);
            if ((lane & 3) == 0) {
                int row = wm * 32 + mt * 16 + (lane >> 2) + rr * 8;
                red[row * 4 + wn] = make_float2(s, q);
            }
        }
    __syncthreads();

#pragma unroll
    for (int mt = 0; mt < 2; ++mt)
#pragma unroll
        for (int rr = 0; rr < 2; ++rr) {
            int row = wm * 32 + mt * 16 + (lane >> 2) + rr * 8;
            float2 r0 = red[row * 4 + 0], r1 = red[row * 4 + 1];
            float2 r2 = red[row * 4 + 2], r3 = red[row * 4 + 3];
            float s = r0.x + r1.x + r2.x + r3.x;
            float q = r0.y + r1.y + r2.y + r3.y;
            float mean = s * 0.0078125f;
            float var  = fmaf(-mean, mean, q * 0.0078125f);
            float rs   = rsqrtf(var + 1e-5f);
            float* orow = out + (size_t)(m0 + row) * NDIM + n0;
#pragma unroll
            for (int nt = 0; nt < 4; ++nt) {
                int n = wn * 32 + nt * 8 + (lane & 3) * 2;
                float2 o;
                o.x = fmaf((acc[mt][nt][rr * 2 + 0] - mean) * rs, gws[n + 0], gbs[n + 0]);
                o.y = fmaf((acc[mt][nt][rr * 2 + 1] - mean) * rs, gws[n + 1], gbs[n + 1]);
                *(float2*)(orow + n) = o;
            }
        }
}

// ---------------- launch ----------------
extern "C" void kernel_launch(void* const* d_in, const int* in_sizes, int n_in,
                              void* d_out, int out_size) {
    const float* x  = (const float*)d_in[0];
    const float* w  = (const float*)d_in[1];
    const float* bl = (const float*)d_in[2];
    const float* be = (const float*)d_in[3];
    const float* gw = (const float*)d_in[4];
    const float* gb = (const float*)d_in[5];
    float* out = (float*)d_out;

    static __half* xh_p = nullptr;
    static __half* wh_p = nullptr;
    if (!xh_p) {
        cudaGetSymbolAddress((void**)&xh_p, g_xh);
        cudaGetSymbolAddress((void**)&wh_p, g_wh);
        cudaFuncSetAttribute(fused_gemm_mish_gn,
                             cudaFuncAttributeMaxDynamicSharedMemorySize, SMEM_BYTES);
    }

    cvt_kernel<<<(int)((size_t)BDIM * KDIM / 8 / 256), 256>>>(x, xh_p);
    cvt_kernel<<<(int)((size_t)NDIM * KDIM / 8 / 256), 256>>>(w, wh_p);

    dim3 grid(NDIM / 128, BDIM / 128);   // (32, 64)
    fused_gemm_mish_gn<<<grid, 512, SMEM_BYTES>>>(bl, be, gw, gb, out);
}